// round 1
// baseline (speedup 1.0000x reference)
#include <cuda_runtime.h>
#include <math.h>

#define BATCH  2
#define SEQ    2048
#define DMODEL 1024
#define NHEAD  16
#define DHEAD  64
#define MTOT   (BATCH * SEQ)   // 4096

// Scratch (allocation-free rule: __device__ globals)
__device__ float g_q[BATCH * NHEAD * SEQ * DHEAD];     // [B,H,S,Dh]
__device__ float g_k[BATCH * NHEAD * SEQ * DHEAD];
__device__ float g_v[BATCH * NHEAD * SEQ * DHEAD];
__device__ float g_attn[BATCH * SEQ * DMODEL];         // [B,S,D] merged heads

// ---------------------------------------------------------------------------
// GEMM: C[m,n] = sum_k X[m,k] * W[n,k] + bias[n]
// X: [M=4096, K=1024] row-major, W: [N=1024, K=1024] row-major (=> X @ W^T)
// Tiling: BM=BN=128, BK=16, 256 threads, 8x8 per-thread register tile.
// dst_sel: 0/1/2 -> g_q/g_k/g_v in [B,H,S,Dh] split-head layout; 3 -> outp [M,N]
// src_sel: 0 -> Xp param; 1 -> g_attn
// ---------------------------------------------------------------------------
__global__ __launch_bounds__(256) void gemm_kernel(
    const float* __restrict__ Xp, const float* __restrict__ W,
    const float* __restrict__ bias, float* __restrict__ outp,
    int src_sel, int dst_sel)
{
    __shared__ float As[16][128];   // [k][m]
    __shared__ float Bs[16][128];   // [k][n]

    const float* X = (src_sel == 0) ? Xp : g_attn;

    const int tid = threadIdx.x;
    const int bm  = blockIdx.y * 128;
    const int bn  = blockIdx.x * 128;
    const int tr  = tid >> 4;    // 0..15 -> rows tr*8..tr*8+7
    const int tc  = tid & 15;    // 0..15 -> cols tc*8..tc*8+7

    float acc[8][8];
#pragma unroll
    for (int i = 0; i < 8; i++)
#pragma unroll
        for (int j = 0; j < 8; j++) acc[i][j] = 0.0f;

    for (int kb = 0; kb < DMODEL; kb += 16) {
        // Load 128x16 tiles of X and W (float4, coalesced), store transposed.
#pragma unroll
        for (int f = tid; f < 512; f += 256) {
            int row = f >> 2;
            int c4  = (f & 3) << 2;
            float4 va = *(const float4*)&X[(bm + row) * DMODEL + kb + c4];
            As[c4 + 0][row] = va.x; As[c4 + 1][row] = va.y;
            As[c4 + 2][row] = va.z; As[c4 + 3][row] = va.w;
            float4 vb = *(const float4*)&W[(bn + row) * DMODEL + kb + c4];
            Bs[c4 + 0][row] = vb.x; Bs[c4 + 1][row] = vb.y;
            Bs[c4 + 2][row] = vb.z; Bs[c4 + 3][row] = vb.w;
        }
        __syncthreads();

#pragma unroll
        for (int k = 0; k < 16; k++) {
            float4 a0 = *(const float4*)&As[k][tr * 8];
            float4 a1 = *(const float4*)&As[k][tr * 8 + 4];
            float4 b0 = *(const float4*)&Bs[k][tc * 8];
            float4 b1 = *(const float4*)&Bs[k][tc * 8 + 4];
            float a[8] = {a0.x, a0.y, a0.z, a0.w, a1.x, a1.y, a1.z, a1.w};
            float b[8] = {b0.x, b0.y, b0.z, b0.w, b1.x, b1.y, b1.z, b1.w};
#pragma unroll
            for (int i = 0; i < 8; i++)
#pragma unroll
                for (int j = 0; j < 8; j++)
                    acc[i][j] += a[i] * b[j];
        }
        __syncthreads();
    }

    // Epilogue
    if (dst_sel == 3) {
#pragma unroll
        for (int i = 0; i < 8; i++) {
            int m = bm + tr * 8 + i;
#pragma unroll
            for (int j = 0; j < 8; j++) {
                int n = bn + tc * 8 + j;
                outp[m * DMODEL + n] = acc[i][j] + bias[n];
            }
        }
    } else {
        float* dst = (dst_sel == 0) ? g_q : ((dst_sel == 1) ? g_k : g_v);
#pragma unroll
        for (int i = 0; i < 8; i++) {
            int m  = bm + tr * 8 + i;
            int bb = m >> 11;           // / SEQ
            int s  = m & (SEQ - 1);
#pragma unroll
            for (int j = 0; j < 8; j++) {
                int n = bn + tc * 8 + j;
                int h = n >> 6;
                int d = n & 63;
                dst[(((bb * NHEAD + h) * SEQ + s) * DHEAD) + d] = acc[i][j] + bias[n];
            }
        }
    }
}

// ---------------------------------------------------------------------------
// Flash attention, fp32, 64-query tiles, online softmax.
// grid: (SEQ/64, NHEAD, BATCH), 256 threads (16x16 -> 4x4 per-thread tiles).
// Smem: Qt (transposed+swizzled), KPt (K transposed+swizzled; reused for P),
//       Vs (row-major). 3 * 16KB = 48KB static.
// Swizzle: elem (row-of-64, col) stored at row*64 + (col ^ (row & 31))
//   -> conflict-free transposed stores AND conflict-free strided reads.
// ---------------------------------------------------------------------------
__global__ __launch_bounds__(256) void flash_kernel()
{
    __shared__ float Qt[64 * 64];   // [d][m] swizzled
    __shared__ float KPt[64 * 64];  // [d][j] swizzled; later [j][r] swizzled (P)
    __shared__ float Vs[64 * 64];   // [j][d] plain

    const int tid = threadIdx.x;
    const int tx  = tid & 15;   // col group
    const int ty  = tid >> 4;   // row group

    const int qt = blockIdx.x;
    const int h  = blockIdx.y;
    const int b  = blockIdx.z;

    const float* qbase = g_q + ((b * NHEAD + h) * SEQ + qt * 64) * DHEAD;
    const float* kbase = g_k + ((b * NHEAD + h) * SEQ) * DHEAD;
    const float* vbase = g_v + ((b * NHEAD + h) * SEQ) * DHEAD;

    // Load Q tile transposed + swizzled
#pragma unroll
    for (int t = tid; t < 4096; t += 256) {
        int r = t >> 6, d = t & 63;
        Qt[d * 64 + (r ^ (d & 31))] = qbase[r * 64 + d];
    }

    float m_run[4], l_run[4], o[4][4];
#pragma unroll
    for (int i = 0; i < 4; i++) {
        m_run[i] = -1e30f;
        l_run[i] = 0.0f;
#pragma unroll
        for (int j = 0; j < 4; j++) o[i][j] = 0.0f;
    }

    const float scale = 0.125f;  // 1/sqrt(64)

    for (int kt = 0; kt < SEQ / 64; kt++) {
        __syncthreads();  // prior-iter PV reads (and Q store on iter 0) complete
        const float* kp = kbase + kt * 64 * DHEAD;
        const float* vp = vbase + kt * 64 * DHEAD;
#pragma unroll
        for (int t = tid; t < 4096; t += 256) {
            int r = t >> 6, d = t & 63;
            KPt[d * 64 + (r ^ (d & 31))] = kp[t];
            Vs[t] = vp[t];
        }
        __syncthreads();

        // S = Q K^T  (4x4 per thread; rows ty*4+i, cols tx*4+j)
        float s[4][4];
#pragma unroll
        for (int i = 0; i < 4; i++)
#pragma unroll
            for (int j = 0; j < 4; j++) s[i][j] = 0.0f;

#pragma unroll 4
        for (int d = 0; d < 64; d++) {
            int sw = d & 31;
            float a[4], bk[4];
#pragma unroll
            for (int i = 0; i < 4; i++) a[i]  = Qt[d * 64 + ((ty * 4 + i) ^ sw)];
#pragma unroll
            for (int j = 0; j < 4; j++) bk[j] = KPt[d * 64 + ((tx * 4 + j) ^ sw)];
#pragma unroll
            for (int i = 0; i < 4; i++)
#pragma unroll
                for (int j = 0; j < 4; j++)
                    s[i][j] += a[i] * bk[j];
        }

        // Online softmax (row reductions over the 16 lanes sharing ty)
#pragma unroll
        for (int i = 0; i < 4; i++) {
            float mx = -1e30f;
#pragma unroll
            for (int j = 0; j < 4; j++) {
                s[i][j] *= scale;
                mx = fmaxf(mx, s[i][j]);
            }
#pragma unroll
            for (int off = 1; off < 16; off <<= 1)
                mx = fmaxf(mx, __shfl_xor_sync(0xffffffffu, mx, off));
            float mnew = fmaxf(m_run[i], mx);
            float sum = 0.0f;
#pragma unroll
            for (int j = 0; j < 4; j++) {
                s[i][j] = __expf(s[i][j] - mnew);
                sum += s[i][j];
            }
#pragma unroll
            for (int off = 1; off < 16; off <<= 1)
                sum += __shfl_xor_sync(0xffffffffu, sum, off);
            float corr = __expf(m_run[i] - mnew);
            l_run[i] = l_run[i] * corr + sum;
            m_run[i] = mnew;
#pragma unroll
            for (int j = 0; j < 4; j++) o[i][j] *= corr;
        }

        __syncthreads();  // all QK^T reads of KPt done before overwrite with P

        // Store P into KPt storage: P[j][r] swizzled
#pragma unroll
        for (int i = 0; i < 4; i++)
#pragma unroll
            for (int jj = 0; jj < 4; jj++) {
                int j = tx * 4 + jj;
                KPt[j * 64 + ((ty * 4 + i) ^ (j & 31))] = s[i][jj];
            }
        __syncthreads();

        // O += P V  (rows ty*4+i, head-dims tx*4+jj)
#pragma unroll 4
        for (int j = 0; j < 64; j++) {
            int sw = j & 31;
            float pp[4], vv[4];
#pragma unroll
            for (int i = 0; i < 4; i++)  pp[i]  = KPt[j * 64 + ((ty * 4 + i) ^ sw)];
#pragma unroll
            for (int jj = 0; jj < 4; jj++) vv[jj] = Vs[j * 64 + tx * 4 + jj];
#pragma unroll
            for (int i = 0; i < 4; i++)
#pragma unroll
                for (int jj = 0; jj < 4; jj++)
                    o[i][jj] += pp[i] * vv[jj];
        }
    }

    // Write normalized output to merged [B,S,D] layout
#pragma unroll
    for (int i = 0; i < 4; i++) {
        int srow = qt * 64 + ty * 4 + i;
        float inv = 1.0f / l_run[i];
#pragma unroll
        for (int jj = 0; jj < 4; jj++) {
            g_attn[(b * SEQ + srow) * DMODEL + h * 64 + tx * 4 + jj] = o[i][jj] * inv;
        }
    }
}

// ---------------------------------------------------------------------------
// Launch: Q/K/V projections -> flash attention -> output projection.
// All on the default stream (sequential dependencies), graph-capturable.
// Inputs: Q,K,V, Wq,bq, Wk,bk, Wv,bv, Wo,bo
// ---------------------------------------------------------------------------
extern "C" void kernel_launch(void* const* d_in, const int* in_sizes, int n_in,
                              void* d_out, int out_size)
{
    const float* Q  = (const float*)d_in[0];
    const float* K  = (const float*)d_in[1];
    const float* V  = (const float*)d_in[2];
    const float* Wq = (const float*)d_in[3];
    const float* bq = (const float*)d_in[4];
    const float* Wk = (const float*)d_in[5];
    const float* bk = (const float*)d_in[6];
    const float* Wv = (const float*)d_in[7];
    const float* bv = (const float*)d_in[8];
    const float* Wo = (const float*)d_in[9];
    const float* bo = (const float*)d_in[10];
    float* out = (float*)d_out;

    dim3 ggrid(DMODEL / 128, MTOT / 128);  // (8, 32)
    gemm_kernel<<<ggrid, 256>>>(Q, Wq, bq, nullptr, 0, 0);
    gemm_kernel<<<ggrid, 256>>>(K, Wk, bk, nullptr, 0, 1);
    gemm_kernel<<<ggrid, 256>>>(V, Wv, bv, nullptr, 0, 2);

    dim3 fgrid(SEQ / 64, NHEAD, BATCH);    // (32, 16, 2)
    flash_kernel<<<fgrid, 256>>>();

    gemm_kernel<<<ggrid, 256>>>(nullptr, Wo, bo, out, 1, 3);
}

// round 3
// speedup vs baseline: 4.2515x; 4.2515x over previous
#include <cuda_runtime.h>
#include <cuda_bf16.h>
#include <cstdint>
#include <math.h>

#define BATCH  2
#define SEQ    2048
#define DMODEL 1024
#define NHEAD  16
#define DHEAD  64
#define MTOT   (BATCH * SEQ)          // 4096
#define XN     (MTOT * DMODEL)        // 4194304
#define WN     (DMODEL * DMODEL)      // 1048576

// ---------------- global scratch (bf16 hi/lo pairs) ----------------
__device__ __nv_bfloat16 g_xh[3][XN];    // converted inputs Q,K,V  [M][K]
__device__ __nv_bfloat16 g_xl[3][XN];
__device__ __nv_bfloat16 g_wh[4][WN];    // converted weights q,k,v,o  [N][K]
__device__ __nv_bfloat16 g_wl[4][WN];
__device__ __nv_bfloat16 g_qkvh[3][XN];  // projected q,k,v  [B,H,S,Dh]
__device__ __nv_bfloat16 g_qkvl[3][XN];
__device__ __nv_bfloat16 g_ah[XN];       // attention out  [B,S,D]
__device__ __nv_bfloat16 g_al[XN];

// ---------------- helpers ----------------
__device__ __forceinline__ uint32_t smem_u32(const void* p) {
    uint32_t a;
    asm("{ .reg .u64 t; cvta.to.shared.u64 t, %1; cvt.u32.u64 %0, t; }" : "=r"(a) : "l"(p));
    return a;
}
// SW128 swizzle for tiles with 128-byte rows (64 bf16). r = row, c = 16B chunk (0..7).
__device__ __forceinline__ uint32_t swz(int r, int c) {
    return (uint32_t)(r * 128 + ((c ^ (r & 7)) * 16));
}
__device__ __forceinline__ void cp16(uint32_t s, const void* g) {
    asm volatile("cp.async.cg.shared.global [%0], [%1], 16;" :: "r"(s), "l"(g));
}
__device__ __forceinline__ void cp_commit() {
    asm volatile("cp.async.commit_group;" ::: "memory");
}
template <int N> __device__ __forceinline__ void cp_wait() {
    asm volatile("cp.async.wait_group %0;" :: "n"(N) : "memory");
}
__device__ __forceinline__ void ldm_x4(uint32_t* r, uint32_t a) {
    asm volatile("ldmatrix.sync.aligned.m8n8.x4.shared.b16 {%0,%1,%2,%3}, [%4];"
                 : "=r"(r[0]), "=r"(r[1]), "=r"(r[2]), "=r"(r[3]) : "r"(a));
}
__device__ __forceinline__ void ldm_x4_t(uint32_t* r, uint32_t a) {
    asm volatile("ldmatrix.sync.aligned.m8n8.x4.trans.shared.b16 {%0,%1,%2,%3}, [%4];"
                 : "=r"(r[0]), "=r"(r[1]), "=r"(r[2]), "=r"(r[3]) : "r"(a));
}
__device__ __forceinline__ void mma16816(float* c, const uint32_t* a, const uint32_t* b) {
    asm volatile("mma.sync.aligned.m16n8k16.row.col.f32.bf16.bf16.f32 "
                 "{%0,%1,%2,%3}, {%4,%5,%6,%7}, {%8,%9}, {%0,%1,%2,%3};"
                 : "+f"(c[0]), "+f"(c[1]), "+f"(c[2]), "+f"(c[3])
                 : "r"(a[0]), "r"(a[1]), "r"(a[2]), "r"(a[3]), "r"(b[0]), "r"(b[1]));
}
// pack two fp32 -> bf16x2 reg, first arg in LOW half
__device__ __forceinline__ uint32_t pack_bf16(float lo, float hi) {
    uint32_t r;
    asm("cvt.rn.bf16x2.f32 %0, %1, %2;" : "=r"(r) : "f"(hi), "f"(lo));
    return r;
}
__device__ __forceinline__ float lo_f(uint32_t u) { return __uint_as_float(u << 16); }
__device__ __forceinline__ float hi_f(uint32_t u) { return __uint_as_float(u & 0xffff0000u); }

// ---------------- convert kernels ----------------
__global__ __launch_bounds__(256) void convert_inputs(
    const float* __restrict__ q, const float* __restrict__ k, const float* __restrict__ v)
{
    const int s = blockIdx.y;
    const float* src = (s == 0) ? q : (s == 1) ? k : v;
    __nv_bfloat16* dh = g_xh[s];
    __nv_bfloat16* dl = g_xl[s];
    int i = (blockIdx.x * 256 + threadIdx.x) * 4;
    float4 x = *(const float4*)&src[i];
    uint32_t h0 = pack_bf16(x.x, x.y), h1 = pack_bf16(x.z, x.w);
    uint32_t l0 = pack_bf16(x.x - lo_f(h0), x.y - hi_f(h0));
    uint32_t l1 = pack_bf16(x.z - lo_f(h1), x.w - hi_f(h1));
    *(uint2*)&dh[i] = make_uint2(h0, h1);
    *(uint2*)&dl[i] = make_uint2(l0, l1);
}

__global__ __launch_bounds__(256) void convert_weights(
    const float* __restrict__ w0, const float* __restrict__ w1,
    const float* __restrict__ w2, const float* __restrict__ w3)
{
    const int s = blockIdx.y;
    const float* src = (s == 0) ? w0 : (s == 1) ? w1 : (s == 2) ? w2 : w3;
    __nv_bfloat16* dh = g_wh[s];
    __nv_bfloat16* dl = g_wl[s];
    int i = (blockIdx.x * 256 + threadIdx.x) * 4;
    float4 x = *(const float4*)&src[i];
    uint32_t h0 = pack_bf16(x.x, x.y), h1 = pack_bf16(x.z, x.w);
    uint32_t l0 = pack_bf16(x.x - lo_f(h0), x.y - hi_f(h0));
    uint32_t l1 = pack_bf16(x.z - lo_f(h1), x.w - hi_f(h1));
    *(uint2*)&dh[i] = make_uint2(h0, h1);
    *(uint2*)&dl[i] = make_uint2(l0, l1);
}

// ---------------- GEMM: C = X @ W^T + b (bf16x3 error-compensated) ----------------
// BM=128, BN=128, BK=64 (4 k16 steps). 256 threads, warp tile 64x32.
// smem/buffer: Ah 16K | Al 16K | Bh 16K | Bl 16K = 64K; double buffered = 128K
#define GEMM_SMEM 131072

__global__ __launch_bounds__(256) void gemm_bf16(
    const float* __restrict__ bias, float* __restrict__ outf, int sel)
{
    extern __shared__ __align__(128) char sm[];
    const uint32_t sb = smem_u32(sm);

    const __nv_bfloat16* Ah_g = (sel < 3) ? g_xh[sel] : g_ah;
    const __nv_bfloat16* Al_g = (sel < 3) ? g_xl[sel] : g_al;
    const __nv_bfloat16* Bh_g = g_wh[sel];
    const __nv_bfloat16* Bl_g = g_wl[sel];

    const int tid = threadIdx.x;
    const int wid = tid >> 5, lane = tid & 31;
    const int bm = blockIdx.y * 128, bn = blockIdx.x * 128;
    const int wm = (wid & 1) * 64;
    const int wn = (wid >> 1) * 32;

    float acc[4][4][4];
#pragma unroll
    for (int a = 0; a < 4; a++)
#pragma unroll
        for (int b = 0; b < 4; b++)
#pragma unroll
            for (int c = 0; c < 4; c++) acc[a][b][c] = 0.0f;

    // ---- tile issue (cp.async) ----
    auto issue = [&](int kb, int buf) {
        uint32_t base = sb + buf * 65536;
        const __nv_bfloat16* gAh = Ah_g + (size_t)bm * DMODEL + kb * 64;
        const __nv_bfloat16* gAl = Al_g + (size_t)bm * DMODEL + kb * 64;
        const __nv_bfloat16* gBh = Bh_g + (size_t)bn * DMODEL + kb * 64;
        const __nv_bfloat16* gBl = Bl_g + (size_t)bn * DMODEL + kb * 64;
#pragma unroll
        for (int i = 0; i < 4; i++) {
            int t = tid + i * 256;          // 0..1023
            int rr = t >> 3, cc = t & 7;
            uint32_t so = swz(rr, cc);
            size_t go = (size_t)rr * DMODEL + cc * 8;
            cp16(base + so,         gAh + go);
            cp16(base + 16384 + so, gAl + go);
            cp16(base + 32768 + so, gBh + go);
            cp16(base + 49152 + so, gBl + go);
        }
    };

    issue(0, 0);
    cp_commit();

    const int sub  = lane >> 3;
    const int rbA  = (sub & 1) * 8 + (lane & 7);
    const int csA  = sub >> 1;
    const int rbB  = (lane >> 4) * 8 + (lane & 7);
    const int csB  = (lane >> 3) & 1;

    for (int kb = 0; kb < 16; kb++) {
        if (kb < 15) {
            issue(kb + 1, (kb + 1) & 1);
            cp_commit();
            cp_wait<1>();
        } else {
            cp_wait<0>();
        }
        __syncthreads();

        const uint32_t base = sb + (kb & 1) * 65536;
#pragma unroll
        for (int kk = 0; kk < 4; kk++) {
            uint32_t ah[4][4], al[4][4], bh[16], bl[16];
            const int chA = kk * 2 + csA;
            const int chB = kk * 2 + csB;
#pragma unroll
            for (int mt = 0; mt < 4; mt++) {
                uint32_t so = swz(wm + mt * 16 + rbA, chA);
                ldm_x4(ah[mt], base + so);
                ldm_x4(al[mt], base + 16384 + so);
            }
#pragma unroll
            for (int p = 0; p < 2; p++) {
                uint32_t so = swz(wn + p * 16 + rbB, chB);
                ldm_x4(&bh[p * 4], base + 32768 + so);
                ldm_x4(&bl[p * 4], base + 49152 + so);
            }
#pragma unroll
            for (int mt = 0; mt < 4; mt++)
#pragma unroll
                for (int nt = 0; nt < 4; nt++) {
                    mma16816(acc[mt][nt], ah[mt], &bh[nt * 2]);
                    mma16816(acc[mt][nt], ah[mt], &bl[nt * 2]);
                    mma16816(acc[mt][nt], al[mt], &bh[nt * 2]);
                }
        }
        __syncthreads();
    }

    // ---- epilogue ----
    if (sel == 3) {
#pragma unroll
        for (int mt = 0; mt < 4; mt++)
#pragma unroll
            for (int nt = 0; nt < 4; nt++) {
                int row = bm + wm + mt * 16 + (lane >> 2);
                int col = bn + wn + nt * 8 + (lane & 3) * 2;
                float2 bv = *(const float2*)&bias[col];
                float2 y01 = make_float2(acc[mt][nt][0] + bv.x, acc[mt][nt][1] + bv.y);
                float2 y23 = make_float2(acc[mt][nt][2] + bv.x, acc[mt][nt][3] + bv.y);
                *(float2*)&outf[(size_t)row * DMODEL + col] = y01;
                *(float2*)&outf[(size_t)(row + 8) * DMODEL + col] = y23;
            }
    } else {
        __nv_bfloat16* dh = g_qkvh[sel];
        __nv_bfloat16* dl = g_qkvl[sel];
#pragma unroll
        for (int mt = 0; mt < 4; mt++)
#pragma unroll
            for (int nt = 0; nt < 4; nt++) {
                int row = bm + wm + mt * 16 + (lane >> 2);
                int col = bn + wn + nt * 8 + (lane & 3) * 2;
                float2 bv = *(const float2*)&bias[col];
                int hh = col >> 6, dd = col & 63;
#pragma unroll
                for (int half = 0; half < 2; half++) {
                    int r = row + half * 8;
                    float y0 = acc[mt][nt][half * 2 + 0] + bv.x;
                    float y1 = acc[mt][nt][half * 2 + 1] + bv.y;
                    uint32_t hp = pack_bf16(y0, y1);
                    uint32_t lp = pack_bf16(y0 - lo_f(hp), y1 - hi_f(hp));
                    int bb = r >> 11, s = r & (SEQ - 1);
                    size_t idx = (((size_t)(bb * NHEAD + hh)) * SEQ + s) * DHEAD + dd;
                    *(uint32_t*)&dh[idx] = hp;
                    *(uint32_t*)&dl[idx] = lp;
                }
            }
    }
}

// ---------------- Flash attention (bf16x3 mma, online softmax) ----------------
// CTA: 128 q rows, 8 warps (16 q rows each). Key tiles of 64, NT=32 iterations.
// smem: Qh 16K | Ql 16K | 2 x (Kh 8K | Kl 8K | Vh 8K | Vl 8K) = 96K
#define FLASH_SMEM 98304

__global__ __launch_bounds__(256) void flash_bf16()
{
    extern __shared__ __align__(128) char sm[];
    const uint32_t sb = smem_u32(sm);

    const int tid = threadIdx.x;
    const int wid = tid >> 5, lane = tid & 31;
    const int qbase = blockIdx.x * 128;
    const int h = blockIdx.y;
    const int b = blockIdx.z;
    const int wq = wid * 16;

    const size_t head = (size_t)(b * NHEAD + h) * SEQ;
    const __nv_bfloat16* qh_g = g_qkvh[0] + (head + qbase) * DHEAD;
    const __nv_bfloat16* ql_g = g_qkvl[0] + (head + qbase) * DHEAD;
    const __nv_bfloat16* kh_g = g_qkvh[1] + head * DHEAD;
    const __nv_bfloat16* kl_g = g_qkvl[1] + head * DHEAD;
    const __nv_bfloat16* vh_g = g_qkvh[2] + head * DHEAD;
    const __nv_bfloat16* vl_g = g_qkvl[2] + head * DHEAD;

    // ---- issue Q (group 0) ----
#pragma unroll
    for (int i = 0; i < 4; i++) {
        int t = tid + i * 256;        // 0..1023
        int rr = t >> 3, cc = t & 7;
        uint32_t so = swz(rr, cc);
        size_t go = (size_t)rr * DHEAD + cc * 8;
        cp16(sb + so, qh_g + go);
        cp16(sb + 16384 + so, ql_g + go);
    }
    cp_commit();

    auto issue_kv = [&](int kt, int buf) {
        uint32_t base = sb + 32768 + buf * 32768;
        size_t k0 = (size_t)kt * 64 * DHEAD;
#pragma unroll
        for (int i = 0; i < 2; i++) {
            int t = tid + i * 256;    // 0..511
            int rr = t >> 3, cc = t & 7;
            uint32_t so = swz(rr, cc);
            size_t go = k0 + (size_t)rr * DHEAD + cc * 8;
            cp16(base + so,         kh_g + go);
            cp16(base + 8192 + so,  kl_g + go);
            cp16(base + 16384 + so, vh_g + go);
            cp16(base + 24576 + so, vl_g + go);
        }
    };

    issue_kv(0, 0);
    cp_commit();

    // wait for Q, load Q fragments into registers
    cp_wait<1>();
    __syncthreads();

    const int sub = lane >> 3;
    const int rbA = (sub & 1) * 8 + (lane & 7);
    const int csA = sub >> 1;
    const int rbB = (lane >> 4) * 8 + (lane & 7);
    const int csB = (lane >> 3) & 1;

    uint32_t qh[4][4], ql[4][4];
#pragma unroll
    for (int kk = 0; kk < 4; kk++) {
        uint32_t so = swz(wq + rbA, kk * 2 + csA);
        ldm_x4(qh[kk], sb + so);
        ldm_x4(ql[kk], sb + 16384 + so);
    }

    float o[8][4];
#pragma unroll
    for (int nt = 0; nt < 8; nt++)
#pragma unroll
        for (int j = 0; j < 4; j++) o[nt][j] = 0.0f;
    float m0 = -1e30f, m1 = -1e30f, l0 = 0.0f, l1 = 0.0f;

    const int NT = SEQ / 64;
    for (int kt = 0; kt < NT; kt++) {
        if (kt < NT - 1) {
            issue_kv(kt + 1, (kt + 1) & 1);
            cp_commit();
            cp_wait<1>();
        } else {
            cp_wait<0>();
        }
        __syncthreads();

        const uint32_t kvb = sb + 32768 + (kt & 1) * 32768;

        // ---- S = Q K^T (m16 x n64 per warp) ----
        float s[8][4];
#pragma unroll
        for (int nt = 0; nt < 8; nt++)
#pragma unroll
            for (int j = 0; j < 4; j++) s[nt][j] = 0.0f;

#pragma unroll
        for (int kk = 0; kk < 4; kk++) {
            uint32_t bh[16], bl[16];
            const int ch = kk * 2 + csB;
#pragma unroll
            for (int p = 0; p < 4; p++) {
                uint32_t so = swz(p * 16 + rbB, ch);
                ldm_x4(&bh[p * 4], kvb + so);
                ldm_x4(&bl[p * 4], kvb + 8192 + so);
            }
#pragma unroll
            for (int nt = 0; nt < 8; nt++) {
                mma16816(s[nt], qh[kk], &bh[nt * 2]);
                mma16816(s[nt], qh[kk], &bl[nt * 2]);
                mma16816(s[nt], ql[kk], &bh[nt * 2]);
            }
        }

        // ---- online softmax (rows lane>>2 and lane>>2 + 8) ----
        float mx0 = -1e30f, mx1 = -1e30f;
#pragma unroll
        for (int nt = 0; nt < 8; nt++) {
            s[nt][0] *= 0.125f; s[nt][1] *= 0.125f;
            s[nt][2] *= 0.125f; s[nt][3] *= 0.125f;
            mx0 = fmaxf(mx0, fmaxf(s[nt][0], s[nt][1]));
            mx1 = fmaxf(mx1, fmaxf(s[nt][2], s[nt][3]));
        }
        mx0 = fmaxf(mx0, __shfl_xor_sync(0xffffffffu, mx0, 1));
        mx0 = fmaxf(mx0, __shfl_xor_sync(0xffffffffu, mx0, 2));
        mx1 = fmaxf(mx1, __shfl_xor_sync(0xffffffffu, mx1, 1));
        mx1 = fmaxf(mx1, __shfl_xor_sync(0xffffffffu, mx1, 2));
        float M0 = fmaxf(m0, mx0), M1 = fmaxf(m1, mx1);
        float c0 = __expf(m0 - M0), c1 = __expf(m1 - M1);
        float sum0 = 0.0f, sum1 = 0.0f;
#pragma unroll
        for (int nt = 0; nt < 8; nt++) {
            s[nt][0] = __expf(s[nt][0] - M0); sum0 += s[nt][0];
            s[nt][1] = __expf(s[nt][1] - M0); sum0 += s[nt][1];
            s[nt][2] = __expf(s[nt][2] - M1); sum1 += s[nt][2];
            s[nt][3] = __expf(s[nt][3] - M1); sum1 += s[nt][3];
        }
        sum0 += __shfl_xor_sync(0xffffffffu, sum0, 1);
        sum0 += __shfl_xor_sync(0xffffffffu, sum0, 2);
        sum1 += __shfl_xor_sync(0xffffffffu, sum1, 1);
        sum1 += __shfl_xor_sync(0xffffffffu, sum1, 2);
        l0 = l0 * c0 + sum0; m0 = M0;
        l1 = l1 * c1 + sum1; m1 = M1;
#pragma unroll
        for (int nt = 0; nt < 8; nt++) {
            o[nt][0] *= c0; o[nt][1] *= c0;
            o[nt][2] *= c1; o[nt][3] *= c1;
        }

        // ---- P fragments (C-frag -> A-frag relabeling, hi/lo split) ----
        uint32_t ph[4][4], pl[4][4];
#pragma unroll
        for (int j = 0; j < 4; j++) {
            const float* e = s[2 * j];
            const float* f = s[2 * j + 1];
            ph[j][0] = pack_bf16(e[0], e[1]);
            ph[j][1] = pack_bf16(e[2], e[3]);
            ph[j][2] = pack_bf16(f[0], f[1]);
            ph[j][3] = pack_bf16(f[2], f[3]);
            pl[j][0] = pack_bf16(e[0] - lo_f(ph[j][0]), e[1] - hi_f(ph[j][0]));
            pl[j][1] = pack_bf16(e[2] - lo_f(ph[j][1]), e[3] - hi_f(ph[j][1]));
            pl[j][2] = pack_bf16(f[0] - lo_f(ph[j][2]), f[1] - hi_f(ph[j][2]));
            pl[j][3] = pack_bf16(f[2] - lo_f(ph[j][3]), f[3] - hi_f(ph[j][3]));
        }

        // ---- O += P V ----
#pragma unroll
        for (int j = 0; j < 4; j++) {
            uint32_t vh[16], vl[16];
#pragma unroll
            for (int i = 0; i < 4; i++) {
                uint32_t so = swz(j * 16 + rbA, 2 * i + csA);
                ldm_x4_t(&vh[i * 4], kvb + 16384 + so);
                ldm_x4_t(&vl[i * 4], kvb + 24576 + so);
            }
#pragma unroll
            for (int nt = 0; nt < 8; nt++) {
                mma16816(o[nt], ph[j], &vh[nt * 2]);
                mma16816(o[nt], ph[j], &vl[nt * 2]);
                mma16816(o[nt], pl[j], &vh[nt * 2]);
            }
        }
        __syncthreads();
    }

    // ---- write attention output as bf16 hi/lo to [B,S,D] ----
    const float inv0 = 1.0f / l0, inv1 = 1.0f / l1;
#pragma unroll
    for (int nt = 0; nt < 8; nt++) {
        int col = h * 64 + nt * 8 + (lane & 3) * 2;
        int row0 = qbase + wq + (lane >> 2);
#pragma unroll
        for (int half = 0; half < 2; half++) {
            int r = row0 + half * 8;
            float inv = half ? inv1 : inv0;
            float y0 = o[nt][half * 2 + 0] * inv;
            float y1 = o[nt][half * 2 + 1] * inv;
            uint32_t hp = pack_bf16(y0, y1);
            uint32_t lp = pack_bf16(y0 - lo_f(hp), y1 - hi_f(hp));
            size_t idx = ((size_t)b * SEQ + r) * DMODEL + col;
            *(uint32_t*)&g_ah[idx] = hp;
            *(uint32_t*)&g_al[idx] = lp;
        }
    }
}

// ---------------- launch ----------------
extern "C" void kernel_launch(void* const* d_in, const int* in_sizes, int n_in,
                              void* d_out, int out_size)
{
    const float* Q  = (const float*)d_in[0];
    const float* K  = (const float*)d_in[1];
    const float* V  = (const float*)d_in[2];
    const float* Wq = (const float*)d_in[3];
    const float* bq = (const float*)d_in[4];
    const float* Wk = (const float*)d_in[5];
    const float* bk = (const float*)d_in[6];
    const float* Wv = (const float*)d_in[7];
    const float* bv = (const float*)d_in[8];
    const float* Wo = (const float*)d_in[9];
    const float* bo = (const float*)d_in[10];
    float* out = (float*)d_out;

    static int attr_done = 0;
    if (!attr_done) {
        cudaFuncSetAttribute(gemm_bf16, cudaFuncAttributeMaxDynamicSharedMemorySize, GEMM_SMEM);
        cudaFuncSetAttribute(flash_bf16, cudaFuncAttributeMaxDynamicSharedMemorySize, FLASH_SMEM);
        attr_done = 1;
    }

    convert_inputs<<<dim3(XN / 4 / 256, 3), 256>>>(Q, K, V);
    convert_weights<<<dim3(WN / 4 / 256, 4), 256>>>(Wq, Wk, Wv, Wo);

    dim3 ggrid(DMODEL / 128, MTOT / 128);   // (8, 32)
    gemm_bf16<<<ggrid, 256, GEMM_SMEM>>>(bq, nullptr, 0);
    gemm_bf16<<<ggrid, 256, GEMM_SMEM>>>(bk, nullptr, 1);
    gemm_bf16<<<ggrid, 256, GEMM_SMEM>>>(bv, nullptr, 2);

    dim3 fgrid(SEQ / 128, NHEAD, BATCH);    // (16, 16, 2)
    flash_bf16<<<fgrid, 256, FLASH_SMEM>>>();

    gemm_bf16<<<ggrid, 256, GEMM_SMEM>>>(bo, out, 3);
}

// round 4
// speedup vs baseline: 6.7108x; 1.5785x over previous
#include <cuda_runtime.h>
#include <cuda_fp16.h>
#include <cstdint>
#include <math.h>

#define BATCH  2
#define SEQ    2048
#define DMODEL 1024
#define NHEAD  16
#define DHEAD  64
#define MTOT   (BATCH * SEQ)          // 4096
#define XN     (MTOT * DMODEL)        // 4194304
#define WN     (DMODEL * DMODEL)      // 1048576

// ---------------- global scratch ----------------
__device__ __half g_xh[3][XN];   // inputs hi  [M][K]
__device__ __half g_xl[3][XN];   // inputs lo
__device__ __half g_w[4][WN];    // weights single fp16 [N][K]
__device__ __half g_qh[XN];      // q (pre-scaled by 0.125) hi/lo  [B,H,S,Dh]
__device__ __half g_ql[XN];
__device__ __half g_kf[XN];      // k single fp16
__device__ __half g_vf[XN];      // v single fp16
__device__ __half g_ah[XN];      // attention out hi/lo [B,S,D]
__device__ __half g_al[XN];

// ---------------- helpers ----------------
__device__ __forceinline__ uint32_t smem_u32(const void* p) {
    uint32_t a;
    asm("{ .reg .u64 t; cvta.to.shared.u64 t, %1; cvt.u32.u64 %0, t; }" : "=r"(a) : "l"(p));
    return a;
}
// swizzle for 128-byte rows (64 fp16). r = row, c = 16B chunk (0..7)
__device__ __forceinline__ uint32_t swz(int r, int c) {
    return (uint32_t)(r * 128 + ((c ^ (r & 7)) * 16));
}
__device__ __forceinline__ void cp16(uint32_t s, const void* g) {
    asm volatile("cp.async.cg.shared.global [%0], [%1], 16;" :: "r"(s), "l"(g));
}
__device__ __forceinline__ void cp_commit() {
    asm volatile("cp.async.commit_group;" ::: "memory");
}
template <int N> __device__ __forceinline__ void cp_wait() {
    asm volatile("cp.async.wait_group %0;" :: "n"(N) : "memory");
}
__device__ __forceinline__ void ldm_x4(uint32_t* r, uint32_t a) {
    asm volatile("ldmatrix.sync.aligned.m8n8.x4.shared.b16 {%0,%1,%2,%3}, [%4];"
                 : "=r"(r[0]), "=r"(r[1]), "=r"(r[2]), "=r"(r[3]) : "r"(a));
}
__device__ __forceinline__ void ldm_x4_t(uint32_t* r, uint32_t a) {
    asm volatile("ldmatrix.sync.aligned.m8n8.x4.trans.shared.b16 {%0,%1,%2,%3}, [%4];"
                 : "=r"(r[0]), "=r"(r[1]), "=r"(r[2]), "=r"(r[3]) : "r"(a));
}
__device__ __forceinline__ void mma16816(float* c, const uint32_t* a, const uint32_t* b) {
    asm volatile("mma.sync.aligned.m16n8k16.row.col.f32.f16.f16.f32 "
                 "{%0,%1,%2,%3}, {%4,%5,%6,%7}, {%8,%9}, {%0,%1,%2,%3};"
                 : "+f"(c[0]), "+f"(c[1]), "+f"(c[2]), "+f"(c[3])
                 : "r"(a[0]), "r"(a[1]), "r"(a[2]), "r"(a[3]), "r"(b[0]), "r"(b[1]));
}
// pack two fp32 -> f16x2, first arg in LOW half (round-3-validated convention)
__device__ __forceinline__ uint32_t pack2h(float lo, float hi) {
    uint32_t r;
    asm("cvt.rn.f16x2.f32 %0, %1, %2;" : "=r"(r) : "f"(hi), "f"(lo));
    return r;
}
__device__ __forceinline__ float lo2f(uint32_t u) {
    __half_raw r; r.x = (unsigned short)(u & 0xffffu);
    return __half2float(*(__half*)&r);
}
__device__ __forceinline__ float hi2f(uint32_t u) {
    __half_raw r; r.x = (unsigned short)(u >> 16);
    return __half2float(*(__half*)&r);
}

// ---------------- convert kernels ----------------
__global__ __launch_bounds__(256) void convert_inputs(
    const float* __restrict__ q, const float* __restrict__ k, const float* __restrict__ v)
{
    const int s = blockIdx.y;
    const float* src = (s == 0) ? q : (s == 1) ? k : v;
    __half* dh = g_xh[s];
    __half* dl = g_xl[s];
    int i = (blockIdx.x * 256 + threadIdx.x) * 4;
    float4 x = *(const float4*)&src[i];
    uint32_t h0 = pack2h(x.x, x.y), h1 = pack2h(x.z, x.w);
    uint32_t l0 = pack2h(x.x - lo2f(h0), x.y - hi2f(h0));
    uint32_t l1 = pack2h(x.z - lo2f(h1), x.w - hi2f(h1));
    *(uint2*)&dh[i] = make_uint2(h0, h1);
    *(uint2*)&dl[i] = make_uint2(l0, l1);
}

__global__ __launch_bounds__(256) void convert_weights(
    const float* __restrict__ w0, const float* __restrict__ w1,
    const float* __restrict__ w2, const float* __restrict__ w3)
{
    const int s = blockIdx.y;
    const float* src = (s == 0) ? w0 : (s == 1) ? w1 : (s == 2) ? w2 : w3;
    __half* dw = g_w[s];
    int i = (blockIdx.x * 256 + threadIdx.x) * 4;
    float4 x = *(const float4*)&src[i];
    *(uint2*)&dw[i] = make_uint2(pack2h(x.x, x.y), pack2h(x.z, x.w));
}

// ---------------- GEMM: C = X @ W^T + b  (fp16 2-term compensated) ----------------
// BM=128, BN=256, BK=64. 256 threads, 8 warps (2m x 4n), warp tile 64x64.
// Stage: Ah 16K | Al 16K | B 32K = 64K; 3 stages = 192K.
#define GSTAGE 65536
#define GSMEM  (3 * GSTAGE)

__global__ __launch_bounds__(256) void gemm_f16(
    const float* __restrict__ b0, const float* __restrict__ b1, const float* __restrict__ b2,
    float* __restrict__ outf, int sel_base)
{
    extern __shared__ __align__(128) char sm[];
    const uint32_t sb = smem_u32(sm);

    const int z = blockIdx.z;
    const int sel = sel_base + z;
    const float* bias = (z == 0) ? b0 : (z == 1) ? b1 : b2;
    const __half* Ah_g = (sel < 3) ? g_xh[sel] : g_ah;
    const __half* Al_g = (sel < 3) ? g_xl[sel] : g_al;
    const __half* B_g  = g_w[sel];

    const int tid = threadIdx.x;
    const int wid = tid >> 5, lane = tid & 31;
    const int bm = blockIdx.y * 128, bn = blockIdx.x * 256;
    const int wm = (wid & 1) * 64;
    const int wn = (wid >> 1) * 64;

    float acc[4][8][4];
#pragma unroll
    for (int a = 0; a < 4; a++)
#pragma unroll
        for (int b = 0; b < 8; b++)
#pragma unroll
            for (int c = 0; c < 4; c++) acc[a][b][c] = 0.0f;

    auto issue = [&](int kb) {
        const uint32_t base = sb + (kb % 3) * GSTAGE;
        const __half* gAh = Ah_g + (size_t)bm * DMODEL + kb * 64;
        const __half* gAl = Al_g + (size_t)bm * DMODEL + kb * 64;
        const __half* gB  = B_g  + (size_t)bn * DMODEL + kb * 64;
#pragma unroll
        for (int i = 0; i < 4; i++) {
            int t = tid + i * 256;           // 0..1023
            int rr = t >> 3, cc = t & 7;
            uint32_t so = swz(rr, cc);
            size_t go = (size_t)rr * DMODEL + cc * 8;
            cp16(base + so,         gAh + go);
            cp16(base + 16384 + so, gAl + go);
        }
#pragma unroll
        for (int i = 0; i < 8; i++) {
            int t = tid + i * 256;           // 0..2047
            int rr = t >> 3, cc = t & 7;
            cp16(base + 32768 + swz(rr, cc), gB + (size_t)rr * DMODEL + cc * 8);
        }
    };

    issue(0); cp_commit();
    issue(1); cp_commit();

    const int sub = lane >> 3;
    const int rbA = (sub & 1) * 8 + (lane & 7);
    const int csA = sub >> 1;
    const int rbB = (lane >> 4) * 8 + (lane & 7);
    const int csB = (lane >> 3) & 1;

    for (int kb = 0; kb < 16; kb++) {
        cp_wait<1>();
        __syncthreads();
        if (kb + 2 < 16) issue(kb + 2);
        cp_commit();

        const uint32_t base = sb + (kb % 3) * GSTAGE;
#pragma unroll
        for (int kk = 0; kk < 4; kk++) {
            uint32_t ah[4][4], al[4][4], bf[16];
            const int chA = kk * 2 + csA;
            const int chB = kk * 2 + csB;
#pragma unroll
            for (int mt = 0; mt < 4; mt++) {
                uint32_t so = swz(wm + mt * 16 + rbA, chA);
                ldm_x4(ah[mt], base + so);
                ldm_x4(al[mt], base + 16384 + so);
            }
#pragma unroll
            for (int p = 0; p < 4; p++) {
                uint32_t so = swz(wn + p * 16 + rbB, chB);
                ldm_x4(&bf[p * 4], base + 32768 + so);
            }
#pragma unroll
            for (int mt = 0; mt < 4; mt++)
#pragma unroll
                for (int nt = 0; nt < 8; nt++) {
                    mma16816(acc[mt][nt], ah[mt], &bf[nt * 2]);
                    mma16816(acc[mt][nt], al[mt], &bf[nt * 2]);
                }
        }
    }

    // ---- epilogue ----
    if (sel == 3) {
#pragma unroll
        for (int mt = 0; mt < 4; mt++)
#pragma unroll
            for (int nt = 0; nt < 8; nt++) {
                int row = bm + wm + mt * 16 + (lane >> 2);
                int col = bn + wn + nt * 8 + (lane & 3) * 2;
                float2 bv = *(const float2*)&bias[col];
                float2 y01 = make_float2(acc[mt][nt][0] + bv.x, acc[mt][nt][1] + bv.y);
                float2 y23 = make_float2(acc[mt][nt][2] + bv.x, acc[mt][nt][3] + bv.y);
                *(float2*)&outf[(size_t)row * DMODEL + col] = y01;
                *(float2*)&outf[(size_t)(row + 8) * DMODEL + col] = y23;
            }
    } else {
#pragma unroll
        for (int mt = 0; mt < 4; mt++)
#pragma unroll
            for (int nt = 0; nt < 8; nt++) {
                int row = bm + wm + mt * 16 + (lane >> 2);
                int col = bn + wn + nt * 8 + (lane & 3) * 2;
                float2 bv = *(const float2*)&bias[col];
                int hh = col >> 6, dd = col & 63;
#pragma unroll
                for (int hf = 0; hf < 2; hf++) {
                    int r = row + hf * 8;
                    float y0 = acc[mt][nt][hf * 2 + 0] + bv.x;
                    float y1 = acc[mt][nt][hf * 2 + 1] + bv.y;
                    int bb = r >> 11, s = r & (SEQ - 1);
                    size_t idx = (((size_t)(bb * NHEAD + hh)) * SEQ + s) * DHEAD + dd;
                    if (sel == 0) {
                        y0 *= 0.125f; y1 *= 0.125f;     // fold 1/sqrt(Dh) into q
                        uint32_t hp = pack2h(y0, y1);
                        uint32_t lp = pack2h(y0 - lo2f(hp), y1 - hi2f(hp));
                        *(uint32_t*)&g_qh[idx] = hp;
                        *(uint32_t*)&g_ql[idx] = lp;
                    } else {
                        uint32_t hp = pack2h(y0, y1);
                        if (sel == 1) *(uint32_t*)&g_kf[idx] = hp;
                        else          *(uint32_t*)&g_vf[idx] = hp;
                    }
                }
            }
    }
}

// ---------------- Flash attention (fp16 2-term, online softmax) ----------------
// CTA: 64 q rows, 4 warps (16 rows each). Key tiles of 64, 3-stage KV pipeline.
// smem: Qh 8K | Ql 8K | 3 x (K 8K | V 8K) = 64K. 2 CTAs/SM.
#define FSTAGE 16384
#define FSMEM  (16384 + 3 * FSTAGE)

__global__ __launch_bounds__(128) void flash_f16()
{
    extern __shared__ __align__(128) char sm[];
    const uint32_t sb = smem_u32(sm);

    const int tid = threadIdx.x;
    const int wid = tid >> 5, lane = tid & 31;
    const int qbase = blockIdx.x * 64;
    const int h = blockIdx.y;
    const int b = blockIdx.z;
    const int wq = wid * 16;

    const size_t head = (size_t)(b * NHEAD + h) * SEQ;
    const __half* qh_g = g_qh + (head + qbase) * DHEAD;
    const __half* ql_g = g_ql + (head + qbase) * DHEAD;
    const __half* kf_g = g_kf + head * DHEAD;
    const __half* vf_g = g_vf + head * DHEAD;

    // ---- issue Q (own group) ----
#pragma unroll
    for (int i = 0; i < 4; i++) {
        int t = tid + i * 128;           // 0..511
        int rr = t >> 3, cc = t & 7;
        uint32_t so = swz(rr, cc);
        size_t go = (size_t)rr * DHEAD + cc * 8;
        cp16(sb + so,        qh_g + go);
        cp16(sb + 8192 + so, ql_g + go);
    }
    cp_commit();

    auto issue_kv = [&](int kt) {
        uint32_t base = sb + 16384 + (kt % 3) * FSTAGE;
        size_t k0 = (size_t)kt * 64 * DHEAD;
#pragma unroll
        for (int i = 0; i < 4; i++) {
            int t = tid + i * 128;       // 0..511
            int rr = t >> 3, cc = t & 7;
            uint32_t so = swz(rr, cc);
            size_t go = k0 + (size_t)rr * DHEAD + cc * 8;
            cp16(base + so,        kf_g + go);
            cp16(base + 8192 + so, vf_g + go);
        }
    };

    issue_kv(0); cp_commit();
    issue_kv(1); cp_commit();

    cp_wait<2>();      // Q ready
    __syncthreads();

    const int sub = lane >> 3;
    const int rbA = (sub & 1) * 8 + (lane & 7);
    const int csA = sub >> 1;
    const int rbB = (lane >> 4) * 8 + (lane & 7);
    const int csB = (lane >> 3) & 1;

    uint32_t qh[4][4], ql[4][4];
#pragma unroll
    for (int kk = 0; kk < 4; kk++) {
        uint32_t so = swz(wq + rbA, kk * 2 + csA);
        ldm_x4(qh[kk], sb + so);
        ldm_x4(ql[kk], sb + 8192 + so);
    }

    float o[8][4];
#pragma unroll
    for (int nt = 0; nt < 8; nt++)
#pragma unroll
        for (int j = 0; j < 4; j++) o[nt][j] = 0.0f;
    float m0 = -1e30f, m1 = -1e30f, l0 = 0.0f, l1 = 0.0f;

    const int NT = SEQ / 64;
    for (int kt = 0; kt < NT; kt++) {
        cp_wait<1>();
        __syncthreads();
        if (kt + 2 < NT) issue_kv(kt + 2);
        cp_commit();

        const uint32_t kvb = sb + 16384 + (kt % 3) * FSTAGE;

        // ---- S = Q K^T (m16 x n64 per warp) ----
        float s[8][4];
#pragma unroll
        for (int nt = 0; nt < 8; nt++)
#pragma unroll
            for (int j = 0; j < 4; j++) s[nt][j] = 0.0f;

#pragma unroll
        for (int kk = 0; kk < 4; kk++) {
            uint32_t kf[16];
            const int ch = kk * 2 + csB;
#pragma unroll
            for (int p = 0; p < 4; p++)
                ldm_x4(&kf[p * 4], kvb + swz(p * 16 + rbB, ch));
#pragma unroll
            for (int nt = 0; nt < 8; nt++) {
                mma16816(s[nt], qh[kk], &kf[nt * 2]);
                mma16816(s[nt], ql[kk], &kf[nt * 2]);
            }
        }

        // ---- online softmax (q pre-scaled; rows lane>>2, lane>>2 + 8) ----
        float mx0 = -1e30f, mx1 = -1e30f;
#pragma unroll
        for (int nt = 0; nt < 8; nt++) {
            mx0 = fmaxf(mx0, fmaxf(s[nt][0], s[nt][1]));
            mx1 = fmaxf(mx1, fmaxf(s[nt][2], s[nt][3]));
        }
        mx0 = fmaxf(mx0, __shfl_xor_sync(0xffffffffu, mx0, 1));
        mx0 = fmaxf(mx0, __shfl_xor_sync(0xffffffffu, mx0, 2));
        mx1 = fmaxf(mx1, __shfl_xor_sync(0xffffffffu, mx1, 1));
        mx1 = fmaxf(mx1, __shfl_xor_sync(0xffffffffu, mx1, 2));
        float M0 = fmaxf(m0, mx0), M1 = fmaxf(m1, mx1);
        float c0 = __expf(m0 - M0), c1 = __expf(m1 - M1);
        float sum0 = 0.0f, sum1 = 0.0f;
#pragma unroll
        for (int nt = 0; nt < 8; nt++) {
            s[nt][0] = __expf(s[nt][0] - M0); sum0 += s[nt][0];
            s[nt][1] = __expf(s[nt][1] - M0); sum0 += s[nt][1];
            s[nt][2] = __expf(s[nt][2] - M1); sum1 += s[nt][2];
            s[nt][3] = __expf(s[nt][3] - M1); sum1 += s[nt][3];
        }
        sum0 += __shfl_xor_sync(0xffffffffu, sum0, 1);
        sum0 += __shfl_xor_sync(0xffffffffu, sum0, 2);
        sum1 += __shfl_xor_sync(0xffffffffu, sum1, 1);
        sum1 += __shfl_xor_sync(0xffffffffu, sum1, 2);
        l0 = l0 * c0 + sum0; m0 = M0;
        l1 = l1 * c1 + sum1; m1 = M1;
#pragma unroll
        for (int nt = 0; nt < 8; nt++) {
            o[nt][0] *= c0; o[nt][1] *= c0;
            o[nt][2] *= c1; o[nt][3] *= c1;
        }

        // ---- P fragments (C-frag -> A-frag relabeling, fp16 hi/lo) ----
        uint32_t ph[4][4], pl[4][4];
#pragma unroll
        for (int j = 0; j < 4; j++) {
            const float* e = s[2 * j];
            const float* f = s[2 * j + 1];
            ph[j][0] = pack2h(e[0], e[1]);
            ph[j][1] = pack2h(e[2], e[3]);
            ph[j][2] = pack2h(f[0], f[1]);
            ph[j][3] = pack2h(f[2], f[3]);
            pl[j][0] = pack2h(e[0] - lo2f(ph[j][0]), e[1] - hi2f(ph[j][0]));
            pl[j][1] = pack2h(e[2] - lo2f(ph[j][1]), e[3] - hi2f(ph[j][1]));
            pl[j][2] = pack2h(f[0] - lo2f(ph[j][2]), f[1] - hi2f(ph[j][2]));
            pl[j][3] = pack2h(f[2] - lo2f(ph[j][3]), f[3] - hi2f(ph[j][3]));
        }

        // ---- O += P V ----
#pragma unroll
        for (int j = 0; j < 4; j++) {
            uint32_t vf[16];
#pragma unroll
            for (int i = 0; i < 4; i++)
                ldm_x4_t(&vf[i * 4], kvb + 8192 + swz(j * 16 + rbA, 2 * i + csA));
#pragma unroll
            for (int nt = 0; nt < 8; nt++) {
                mma16816(o[nt], ph[j], &vf[nt * 2]);
                mma16816(o[nt], pl[j], &vf[nt * 2]);
            }
        }
    }

    // ---- write attention output hi/lo to [B,S,D] ----
    const float inv0 = 1.0f / l0, inv1 = 1.0f / l1;
#pragma unroll
    for (int nt = 0; nt < 8; nt++) {
        int col = h * 64 + nt * 8 + (lane & 3) * 2;
        int row0 = qbase + wq + (lane >> 2);
#pragma unroll
        for (int hf = 0; hf < 2; hf++) {
            int r = row0 + hf * 8;
            float inv = hf ? inv1 : inv0;
            float y0 = o[nt][hf * 2 + 0] * inv;
            float y1 = o[nt][hf * 2 + 1] * inv;
            uint32_t hp = pack2h(y0, y1);
            uint32_t lp = pack2h(y0 - lo2f(hp), y1 - hi2f(hp));
            size_t idx = ((size_t)b * SEQ + r) * DMODEL + col;
            *(uint32_t*)&g_ah[idx] = hp;
            *(uint32_t*)&g_al[idx] = lp;
        }
    }
}

// ---------------- launch ----------------
extern "C" void kernel_launch(void* const* d_in, const int* in_sizes, int n_in,
                              void* d_out, int out_size)
{
    const float* Q  = (const float*)d_in[0];
    const float* K  = (const float*)d_in[1];
    const float* V  = (const float*)d_in[2];
    const float* Wq = (const float*)d_in[3];
    const float* bq = (const float*)d_in[4];
    const float* Wk = (const float*)d_in[5];
    const float* bk = (const float*)d_in[6];
    const float* Wv = (const float*)d_in[7];
    const float* bv = (const float*)d_in[8];
    const float* Wo = (const float*)d_in[9];
    const float* bo = (const float*)d_in[10];
    float* out = (float*)d_out;

    static int attr_done = 0;
    if (!attr_done) {
        cudaFuncSetAttribute(gemm_f16, cudaFuncAttributeMaxDynamicSharedMemorySize, GSMEM);
        cudaFuncSetAttribute(flash_f16, cudaFuncAttributeMaxDynamicSharedMemorySize, FSMEM);
        attr_done = 1;
    }

    convert_inputs<<<dim3(XN / 4 / 256, 3), 256>>>(Q, K, V);
    convert_weights<<<dim3(WN / 4 / 256, 4), 256>>>(Wq, Wk, Wv, Wo);

    // Q, K, V projections in one launch (grid.z = sel)
    gemm_f16<<<dim3(DMODEL / 256, MTOT / 128, 3), 256, GSMEM>>>(bq, bk, bv, nullptr, 0);

    flash_f16<<<dim3(SEQ / 64, NHEAD, BATCH), 128, FSMEM>>>();

    // output projection
    gemm_f16<<<dim3(DMODEL / 256, MTOT / 128, 1), 256, GSMEM>>>(bo, bo, bo, out, 3);
}

// round 5
// speedup vs baseline: 11.2611x; 1.6780x over previous
#include <cuda_runtime.h>
#include <cuda_fp16.h>
#include <cstdint>
#include <math.h>

#define BATCH  2
#define SEQ    2048
#define DMODEL 1024
#define NHEAD  16
#define DHEAD  64
#define MTOT   (BATCH * SEQ)          // 4096
#define XN     (MTOT * DMODEL)        // 4194304
#define WN     (DMODEL * DMODEL)      // 1048576

// ---------------- global scratch (single fp16) ----------------
__device__ __half g_x[3][XN];    // converted inputs  [M][K]
__device__ __half g_w[4][WN];    // converted weights [N][K]
__device__ __half g_qf[XN];      // q (pre-scaled by 0.125) [B,H,S,Dh]
__device__ __half g_kf[XN];      // k
__device__ __half g_vf[XN];      // v
__device__ __half g_af[XN];      // attention out [B,S,D]

// ---------------- helpers ----------------
__device__ __forceinline__ uint32_t smem_u32(const void* p) {
    uint32_t a;
    asm("{ .reg .u64 t; cvta.to.shared.u64 t, %1; cvt.u32.u64 %0, t; }" : "=r"(a) : "l"(p));
    return a;
}
// swizzle for 128-byte rows (64 fp16). r = row, c = 16B chunk (0..7)
__device__ __forceinline__ uint32_t swz(int r, int c) {
    return (uint32_t)(r * 128 + ((c ^ (r & 7)) * 16));
}
__device__ __forceinline__ void cp16(uint32_t s, const void* g) {
    asm volatile("cp.async.cg.shared.global [%0], [%1], 16;" :: "r"(s), "l"(g));
}
__device__ __forceinline__ void cp_commit() {
    asm volatile("cp.async.commit_group;" ::: "memory");
}
template <int N> __device__ __forceinline__ void cp_wait() {
    asm volatile("cp.async.wait_group %0;" :: "n"(N) : "memory");
}
__device__ __forceinline__ void ldm_x4(uint32_t* r, uint32_t a) {
    asm volatile("ldmatrix.sync.aligned.m8n8.x4.shared.b16 {%0,%1,%2,%3}, [%4];"
                 : "=r"(r[0]), "=r"(r[1]), "=r"(r[2]), "=r"(r[3]) : "r"(a));
}
__device__ __forceinline__ void ldm_x4_t(uint32_t* r, uint32_t a) {
    asm volatile("ldmatrix.sync.aligned.m8n8.x4.trans.shared.b16 {%0,%1,%2,%3}, [%4];"
                 : "=r"(r[0]), "=r"(r[1]), "=r"(r[2]), "=r"(r[3]) : "r"(a));
}
__device__ __forceinline__ void mma16816(float* c, const uint32_t* a, const uint32_t* b) {
    asm volatile("mma.sync.aligned.m16n8k16.row.col.f32.f16.f16.f32 "
                 "{%0,%1,%2,%3}, {%4,%5,%6,%7}, {%8,%9}, {%0,%1,%2,%3};"
                 : "+f"(c[0]), "+f"(c[1]), "+f"(c[2]), "+f"(c[3])
                 : "r"(a[0]), "r"(a[1]), "r"(a[2]), "r"(a[3]), "r"(b[0]), "r"(b[1]));
}
// pack two fp32 -> f16x2, first arg in LOW half
__device__ __forceinline__ uint32_t pack2h(float lo, float hi) {
    uint32_t r;
    asm("cvt.rn.f16x2.f32 %0, %1, %2;" : "=r"(r) : "f"(hi), "f"(lo));
    return r;
}

// ---------------- convert kernels ----------------
__global__ __launch_bounds__(256) void convert_inputs(
    const float* __restrict__ q, const float* __restrict__ k, const float* __restrict__ v)
{
    const int s = blockIdx.y;
    const float* src = (s == 0) ? q : (s == 1) ? k : v;
    __half* d = g_x[s];
    int i = (blockIdx.x * 256 + threadIdx.x) * 8;
    float4 x0 = *(const float4*)&src[i];
    float4 x1 = *(const float4*)&src[i + 4];
    uint4 o;
    o.x = pack2h(x0.x, x0.y); o.y = pack2h(x0.z, x0.w);
    o.z = pack2h(x1.x, x1.y); o.w = pack2h(x1.z, x1.w);
    *(uint4*)&d[i] = o;
}

__global__ __launch_bounds__(256) void convert_weights(
    const float* __restrict__ w0, const float* __restrict__ w1,
    const float* __restrict__ w2, const float* __restrict__ w3)
{
    const int s = blockIdx.y;
    const float* src = (s == 0) ? w0 : (s == 1) ? w1 : (s == 2) ? w2 : w3;
    __half* d = g_w[s];
    int i = (blockIdx.x * 256 + threadIdx.x) * 8;
    float4 x0 = *(const float4*)&src[i];
    float4 x1 = *(const float4*)&src[i + 4];
    uint4 o;
    o.x = pack2h(x0.x, x0.y); o.y = pack2h(x0.z, x0.w);
    o.z = pack2h(x1.x, x1.y); o.w = pack2h(x1.z, x1.w);
    *(uint4*)&d[i] = o;
}

// ---------------- GEMM: C = X @ W^T + b (single fp16) ----------------
// BM=128, BN=256, BK=64. 256 threads, 8 warps (2m x 4n), warp tile 64x64.
// Stage: A 16K | B 32K = 48K; 4 stages = 192K.
#define GSTAGE 49152
#define GSMEM  (4 * GSTAGE)

__global__ __launch_bounds__(256) void gemm_f16(
    const float* __restrict__ b0, const float* __restrict__ b1, const float* __restrict__ b2,
    float* __restrict__ outf, int sel_base)
{
    extern __shared__ __align__(128) char sm[];
    const uint32_t sb = smem_u32(sm);

    const int z = blockIdx.z;
    const int sel = sel_base + z;
    const float* bias = (z == 0) ? b0 : (z == 1) ? b1 : b2;
    const __half* A_g = (sel < 3) ? g_x[sel] : g_af;
    const __half* B_g = g_w[sel];

    const int tid = threadIdx.x;
    const int wid = tid >> 5, lane = tid & 31;
    const int bm = blockIdx.y * 128, bn = blockIdx.x * 256;
    const int wm = (wid & 1) * 64;
    const int wn = (wid >> 1) * 64;

    float acc[4][8][4];
#pragma unroll
    for (int a = 0; a < 4; a++)
#pragma unroll
        for (int b = 0; b < 8; b++)
#pragma unroll
            for (int c = 0; c < 4; c++) acc[a][b][c] = 0.0f;

    auto issue = [&](int kb) {
        const uint32_t base = sb + (kb & 3) * GSTAGE;
        const __half* gA = A_g + (size_t)bm * DMODEL + kb * 64;
        const __half* gB = B_g + (size_t)bn * DMODEL + kb * 64;
#pragma unroll
        for (int i = 0; i < 4; i++) {
            int t = tid + i * 256;           // 0..1023
            int rr = t >> 3, cc = t & 7;
            cp16(base + swz(rr, cc), gA + (size_t)rr * DMODEL + cc * 8);
        }
#pragma unroll
        for (int i = 0; i < 8; i++) {
            int t = tid + i * 256;           // 0..2047
            int rr = t >> 3, cc = t & 7;
            cp16(base + 16384 + swz(rr, cc), gB + (size_t)rr * DMODEL + cc * 8);
        }
    };

    issue(0); cp_commit();
    issue(1); cp_commit();
    issue(2); cp_commit();

    const int sub = lane >> 3;
    const int rbA = (sub & 1) * 8 + (lane & 7);
    const int csA = sub >> 1;
    const int rbB = (lane >> 4) * 8 + (lane & 7);
    const int csB = (lane >> 3) & 1;

    for (int kb = 0; kb < 16; kb++) {
        cp_wait<2>();
        __syncthreads();
        if (kb + 3 < 16) issue(kb + 3);
        cp_commit();

        const uint32_t base = sb + (kb & 3) * GSTAGE;
#pragma unroll
        for (int kk = 0; kk < 4; kk++) {
            uint32_t af[4][4], bf[16];
            const int chA = kk * 2 + csA;
            const int chB = kk * 2 + csB;
#pragma unroll
            for (int mt = 0; mt < 4; mt++)
                ldm_x4(af[mt], base + swz(wm + mt * 16 + rbA, chA));
#pragma unroll
            for (int p = 0; p < 4; p++)
                ldm_x4(&bf[p * 4], base + 16384 + swz(wn + p * 16 + rbB, chB));
#pragma unroll
            for (int mt = 0; mt < 4; mt++)
#pragma unroll
                for (int nt = 0; nt < 8; nt++)
                    mma16816(acc[mt][nt], af[mt], &bf[nt * 2]);
        }
        __syncthreads();
    }

    // ---- epilogue ----
    if (sel == 3) {
#pragma unroll
        for (int mt = 0; mt < 4; mt++)
#pragma unroll
            for (int nt = 0; nt < 8; nt++) {
                int row = bm + wm + mt * 16 + (lane >> 2);
                int col = bn + wn + nt * 8 + (lane & 3) * 2;
                float2 bv = *(const float2*)&bias[col];
                float2 y01 = make_float2(acc[mt][nt][0] + bv.x, acc[mt][nt][1] + bv.y);
                float2 y23 = make_float2(acc[mt][nt][2] + bv.x, acc[mt][nt][3] + bv.y);
                *(float2*)&outf[(size_t)row * DMODEL + col] = y01;
                *(float2*)&outf[(size_t)(row + 8) * DMODEL + col] = y23;
            }
    } else {
        __half* dst = (sel == 0) ? g_qf : (sel == 1) ? g_kf : g_vf;
        const float qs = (sel == 0) ? 0.125f : 1.0f;
#pragma unroll
        for (int mt = 0; mt < 4; mt++)
#pragma unroll
            for (int nt = 0; nt < 8; nt++) {
                int row = bm + wm + mt * 16 + (lane >> 2);
                int col = bn + wn + nt * 8 + (lane & 3) * 2;
                float2 bv = *(const float2*)&bias[col];
                int hh = col >> 6, dd = col & 63;
#pragma unroll
                for (int hf = 0; hf < 2; hf++) {
                    int r = row + hf * 8;
                    float y0 = (acc[mt][nt][hf * 2 + 0] + bv.x) * qs;
                    float y1 = (acc[mt][nt][hf * 2 + 1] + bv.y) * qs;
                    int bb = r >> 11, s = r & (SEQ - 1);
                    size_t idx = (((size_t)(bb * NHEAD + hh)) * SEQ + s) * DHEAD + dd;
                    *(uint32_t*)&dst[idx] = pack2h(y0, y1);
                }
            }
    }
}

// ---------------- Flash attention (single fp16, online softmax) ----------------
// CTA: 64 q rows, 4 warps (16 rows each). Key tiles of 64, 3-stage KV pipeline.
// smem: Q 8K | 3 x (K 8K | V 8K) = 56K -> up to 4 CTAs/SM.
#define FSTAGE 16384
#define FSMEM  (8192 + 3 * FSTAGE)

__global__ __launch_bounds__(128) void flash_f16()
{
    extern __shared__ __align__(128) char sm[];
    const uint32_t sb = smem_u32(sm);

    const int tid = threadIdx.x;
    const int wid = tid >> 5, lane = tid & 31;
    const int qbase = blockIdx.x * 64;
    const int h = blockIdx.y;
    const int b = blockIdx.z;
    const int wq = wid * 16;

    const size_t head = (size_t)(b * NHEAD + h) * SEQ;
    const __half* qf_g = g_qf + (head + qbase) * DHEAD;
    const __half* kf_g = g_kf + head * DHEAD;
    const __half* vf_g = g_vf + head * DHEAD;

    // ---- issue Q ----
#pragma unroll
    for (int i = 0; i < 4; i++) {
        int t = tid + i * 128;           // 0..511
        int rr = t >> 3, cc = t & 7;
        cp16(sb + swz(rr, cc), qf_g + (size_t)rr * DHEAD + cc * 8);
    }
    cp_commit();

    auto issue_kv = [&](int kt) {
        uint32_t base = sb + 8192 + (kt % 3) * FSTAGE;
        size_t k0 = (size_t)kt * 64 * DHEAD;
#pragma unroll
        for (int i = 0; i < 4; i++) {
            int t = tid + i * 128;       // 0..511
            int rr = t >> 3, cc = t & 7;
            uint32_t so = swz(rr, cc);
            size_t go = k0 + (size_t)rr * DHEAD + cc * 8;
            cp16(base + so,        kf_g + go);
            cp16(base + 8192 + so, vf_g + go);
        }
    };

    issue_kv(0); cp_commit();
    issue_kv(1); cp_commit();

    cp_wait<2>();      // Q ready
    __syncthreads();

    const int sub = lane >> 3;
    const int rbA = (sub & 1) * 8 + (lane & 7);
    const int csA = sub >> 1;
    const int rbB = (lane >> 4) * 8 + (lane & 7);
    const int csB = (lane >> 3) & 1;

    uint32_t qf[4][4];
#pragma unroll
    for (int kk = 0; kk < 4; kk++)
        ldm_x4(qf[kk], sb + swz(wq + rbA, kk * 2 + csA));

    float o[8][4];
#pragma unroll
    for (int nt = 0; nt < 8; nt++)
#pragma unroll
        for (int j = 0; j < 4; j++) o[nt][j] = 0.0f;
    float m0 = -1e30f, m1 = -1e30f, l0 = 0.0f, l1 = 0.0f;

    const int NT = SEQ / 64;
    for (int kt = 0; kt < NT; kt++) {
        cp_wait<1>();
        __syncthreads();
        if (kt + 2 < NT) issue_kv(kt + 2);
        cp_commit();

        const uint32_t kvb = sb + 8192 + (kt % 3) * FSTAGE;

        // ---- S = Q K^T (m16 x n64 per warp) ----
        float s[8][4];
#pragma unroll
        for (int nt = 0; nt < 8; nt++)
#pragma unroll
            for (int j = 0; j < 4; j++) s[nt][j] = 0.0f;

#pragma unroll
        for (int kk = 0; kk < 4; kk++) {
            uint32_t kf[16];
            const int ch = kk * 2 + csB;
#pragma unroll
            for (int p = 0; p < 4; p++)
                ldm_x4(&kf[p * 4], kvb + swz(p * 16 + rbB, ch));
#pragma unroll
            for (int nt = 0; nt < 8; nt++)
                mma16816(s[nt], qf[kk], &kf[nt * 2]);
        }

        // ---- online softmax (q pre-scaled; rows lane>>2, lane>>2 + 8) ----
        float mx0 = -1e30f, mx1 = -1e30f;
#pragma unroll
        for (int nt = 0; nt < 8; nt++) {
            mx0 = fmaxf(mx0, fmaxf(s[nt][0], s[nt][1]));
            mx1 = fmaxf(mx1, fmaxf(s[nt][2], s[nt][3]));
        }
        mx0 = fmaxf(mx0, __shfl_xor_sync(0xffffffffu, mx0, 1));
        mx0 = fmaxf(mx0, __shfl_xor_sync(0xffffffffu, mx0, 2));
        mx1 = fmaxf(mx1, __shfl_xor_sync(0xffffffffu, mx1, 1));
        mx1 = fmaxf(mx1, __shfl_xor_sync(0xffffffffu, mx1, 2));
        float M0 = fmaxf(m0, mx0), M1 = fmaxf(m1, mx1);
        float c0 = __expf(m0 - M0), c1 = __expf(m1 - M1);
        float sum0 = 0.0f, sum1 = 0.0f;
#pragma unroll
        for (int nt = 0; nt < 8; nt++) {
            s[nt][0] = __expf(s[nt][0] - M0); sum0 += s[nt][0];
            s[nt][1] = __expf(s[nt][1] - M0); sum0 += s[nt][1];
            s[nt][2] = __expf(s[nt][2] - M1); sum1 += s[nt][2];
            s[nt][3] = __expf(s[nt][3] - M1); sum1 += s[nt][3];
        }
        sum0 += __shfl_xor_sync(0xffffffffu, sum0, 1);
        sum0 += __shfl_xor_sync(0xffffffffu, sum0, 2);
        sum1 += __shfl_xor_sync(0xffffffffu, sum1, 1);
        sum1 += __shfl_xor_sync(0xffffffffu, sum1, 2);
        l0 = l0 * c0 + sum0; m0 = M0;
        l1 = l1 * c1 + sum1; m1 = M1;
#pragma unroll
        for (int nt = 0; nt < 8; nt++) {
            o[nt][0] *= c0; o[nt][1] *= c0;
            o[nt][2] *= c1; o[nt][3] *= c1;
        }

        // ---- P fragments (C-frag -> A-frag relabeling) ----
        uint32_t pf[4][4];
#pragma unroll
        for (int j = 0; j < 4; j++) {
            const float* e = s[2 * j];
            const float* f = s[2 * j + 1];
            pf[j][0] = pack2h(e[0], e[1]);
            pf[j][1] = pack2h(e[2], e[3]);
            pf[j][2] = pack2h(f[0], f[1]);
            pf[j][3] = pack2h(f[2], f[3]);
        }

        // ---- O += P V ----
#pragma unroll
        for (int j = 0; j < 4; j++) {
            uint32_t vf[16];
#pragma unroll
            for (int i = 0; i < 4; i++)
                ldm_x4_t(&vf[i * 4], kvb + 8192 + swz(j * 16 + rbA, 2 * i + csA));
#pragma unroll
            for (int nt = 0; nt < 8; nt++)
                mma16816(o[nt], pf[j], &vf[nt * 2]);
        }
    }

    // ---- write attention output to [B,S,D] (single fp16) ----
    const float inv0 = 1.0f / l0, inv1 = 1.0f / l1;
#pragma unroll
    for (int nt = 0; nt < 8; nt++) {
        int col = h * 64 + nt * 8 + (lane & 3) * 2;
        int row0 = qbase + wq + (lane >> 2);
#pragma unroll
        for (int hf = 0; hf < 2; hf++) {
            int r = row0 + hf * 8;
            float inv = hf ? inv1 : inv0;
            float y0 = o[nt][hf * 2 + 0] * inv;
            float y1 = o[nt][hf * 2 + 1] * inv;
            size_t idx = ((size_t)b * SEQ + r) * DMODEL + col;
            *(uint32_t*)&g_af[idx] = pack2h(y0, y1);
        }
    }
}

// ---------------- launch ----------------
extern "C" void kernel_launch(void* const* d_in, const int* in_sizes, int n_in,
                              void* d_out, int out_size)
{
    const float* Q  = (const float*)d_in[0];
    const float* K  = (const float*)d_in[1];
    const float* V  = (const float*)d_in[2];
    const float* Wq = (const float*)d_in[3];
    const float* bq = (const float*)d_in[4];
    const float* Wk = (const float*)d_in[5];
    const float* bk = (const float*)d_in[6];
    const float* Wv = (const float*)d_in[7];
    const float* bv = (const float*)d_in[8];
    const float* Wo = (const float*)d_in[9];
    const float* bo = (const float*)d_in[10];
    float* out = (float*)d_out;

    static int attr_done = 0;
    if (!attr_done) {
        cudaFuncSetAttribute(gemm_f16, cudaFuncAttributeMaxDynamicSharedMemorySize, GSMEM);
        cudaFuncSetAttribute(flash_f16, cudaFuncAttributeMaxDynamicSharedMemorySize, FSMEM);
        attr_done = 1;
    }

    convert_inputs<<<dim3(XN / 8 / 256, 3), 256>>>(Q, K, V);
    convert_weights<<<dim3(WN / 8 / 256, 4), 256>>>(Wq, Wk, Wv, Wo);

    // Q, K, V projections in one launch (grid.z = sel)
    gemm_f16<<<dim3(DMODEL / 256, MTOT / 128, 3), 256, GSMEM>>>(bq, bk, bv, nullptr, 0);

    flash_f16<<<dim3(SEQ / 64, NHEAD, BATCH), 128, FSMEM>>>();

    // output projection
    gemm_f16<<<dim3(DMODEL / 256, MTOT / 128, 1), 256, GSMEM>>>(bo, bo, bo, out, 3);
}

// round 6
// speedup vs baseline: 11.3649x; 1.0092x over previous
#include <cuda_runtime.h>
#include <cuda_fp16.h>
#include <cstdint>
#include <math.h>

#define BATCH  2
#define SEQ    2048
#define DMODEL 1024
#define NHEAD  16
#define DHEAD  64
#define MTOT   (BATCH * SEQ)          // 4096
#define XN     (MTOT * DMODEL)        // 4194304
#define WN     (DMODEL * DMODEL)      // 1048576

// ---------------- global scratch (single fp16) ----------------
__device__ __half g_x[3][XN];    // converted inputs  [M][K]
__device__ __half g_w[4][WN];    // converted weights [N][K]
__device__ __half g_qf[XN];      // q (pre-scaled by 0.125*log2e) [B,H,S,Dh]
__device__ __half g_kf[XN];      // k
__device__ __half g_vf[XN];      // v
__device__ __half g_af[XN];      // attention out [B,S,D]

// ---------------- helpers ----------------
__device__ __forceinline__ uint32_t smem_u32(const void* p) {
    uint32_t a;
    asm("{ .reg .u64 t; cvta.to.shared.u64 t, %1; cvt.u32.u64 %0, t; }" : "=r"(a) : "l"(p));
    return a;
}
// swizzle for 128-byte rows (64 fp16). r = row, c = 16B chunk (0..7)
__device__ __forceinline__ uint32_t swz(int r, int c) {
    return (uint32_t)(r * 128 + ((c ^ (r & 7)) * 16));
}
__device__ __forceinline__ void cp16(uint32_t s, const void* g) {
    asm volatile("cp.async.cg.shared.global [%0], [%1], 16;" :: "r"(s), "l"(g));
}
__device__ __forceinline__ void cp_commit() {
    asm volatile("cp.async.commit_group;" ::: "memory");
}
template <int N> __device__ __forceinline__ void cp_wait() {
    asm volatile("cp.async.wait_group %0;" :: "n"(N) : "memory");
}
__device__ __forceinline__ void ldm_x4(uint32_t* r, uint32_t a) {
    asm volatile("ldmatrix.sync.aligned.m8n8.x4.shared.b16 {%0,%1,%2,%3}, [%4];"
                 : "=r"(r[0]), "=r"(r[1]), "=r"(r[2]), "=r"(r[3]) : "r"(a));
}
__device__ __forceinline__ void ldm_x4_t(uint32_t* r, uint32_t a) {
    asm volatile("ldmatrix.sync.aligned.m8n8.x4.trans.shared.b16 {%0,%1,%2,%3}, [%4];"
                 : "=r"(r[0]), "=r"(r[1]), "=r"(r[2]), "=r"(r[3]) : "r"(a));
}
__device__ __forceinline__ void mma16816(float* c, const uint32_t* a, const uint32_t* b) {
    asm volatile("mma.sync.aligned.m16n8k16.row.col.f32.f16.f16.f32 "
                 "{%0,%1,%2,%3}, {%4,%5,%6,%7}, {%8,%9}, {%0,%1,%2,%3};"
                 : "+f"(c[0]), "+f"(c[1]), "+f"(c[2]), "+f"(c[3])
                 : "r"(a[0]), "r"(a[1]), "r"(a[2]), "r"(a[3]), "r"(b[0]), "r"(b[1]));
}
// pack two fp32 -> f16x2, first arg in LOW half
__device__ __forceinline__ uint32_t pack2h(float lo, float hi) {
    uint32_t r;
    asm("cvt.rn.f16x2.f32 %0, %1, %2;" : "=r"(r) : "f"(hi), "f"(lo));
    return r;
}

// ---------------- convert kernels ----------------
__global__ __launch_bounds__(256) void convert_inputs(
    const float* __restrict__ q, const float* __restrict__ k, const float* __restrict__ v)
{
    const int s = blockIdx.y;
    const float* src = (s == 0) ? q : (s == 1) ? k : v;
    __half* d = g_x[s];
    int i = (blockIdx.x * 256 + threadIdx.x) * 8;
    float4 x0 = *(const float4*)&src[i];
    float4 x1 = *(const float4*)&src[i + 4];
    uint4 o;
    o.x = pack2h(x0.x, x0.y); o.y = pack2h(x0.z, x0.w);
    o.z = pack2h(x1.x, x1.y); o.w = pack2h(x1.z, x1.w);
    *(uint4*)&d[i] = o;
}

__global__ __launch_bounds__(256) void convert_weights(
    const float* __restrict__ w0, const float* __restrict__ w1,
    const float* __restrict__ w2, const float* __restrict__ w3)
{
    const int s = blockIdx.y;
    const float* src = (s == 0) ? w0 : (s == 1) ? w1 : (s == 2) ? w2 : w3;
    __half* d = g_w[s];
    int i = (blockIdx.x * 256 + threadIdx.x) * 8;
    float4 x0 = *(const float4*)&src[i];
    float4 x1 = *(const float4*)&src[i + 4];
    uint4 o;
    o.x = pack2h(x0.x, x0.y); o.y = pack2h(x0.z, x0.w);
    o.z = pack2h(x1.x, x1.y); o.w = pack2h(x1.z, x1.w);
    *(uint4*)&d[i] = o;
}

// ---------------- GEMM: C = X @ W^T + b (single fp16) ----------------
// BM=128, BN=256, BK=64. 256 threads, 8 warps (2m x 4n), warp tile 64x64.
// Stage: A 16K | B 32K = 48K; 2 stages = 96K -> 2 CTAs/SM.
#define GSTAGE 49152
#define GSMEM  (2 * GSTAGE)

__global__ __launch_bounds__(256) void gemm_f16(
    const float* __restrict__ b0, const float* __restrict__ b1, const float* __restrict__ b2,
    float* __restrict__ outf, int sel_base)
{
    extern __shared__ __align__(128) char sm[];
    const uint32_t sb = smem_u32(sm);

    const int z = blockIdx.z;
    const int sel = sel_base + z;
    const float* bias = (z == 0) ? b0 : (z == 1) ? b1 : b2;
    const __half* A_g = (sel < 3) ? g_x[sel] : g_af;
    const __half* B_g = g_w[sel];

    const int tid = threadIdx.x;
    const int wid = tid >> 5, lane = tid & 31;
    const int bm = blockIdx.y * 128, bn = blockIdx.x * 256;
    const int wm = (wid & 1) * 64;
    const int wn = (wid >> 1) * 64;

    float acc[4][8][4];
#pragma unroll
    for (int a = 0; a < 4; a++)
#pragma unroll
        for (int b = 0; b < 8; b++)
#pragma unroll
            for (int c = 0; c < 4; c++) acc[a][b][c] = 0.0f;

    auto issue = [&](int kb) {
        const uint32_t base = sb + (kb & 1) * GSTAGE;
        const __half* gA = A_g + (size_t)bm * DMODEL + kb * 64;
        const __half* gB = B_g + (size_t)bn * DMODEL + kb * 64;
#pragma unroll
        for (int i = 0; i < 4; i++) {
            int t = tid + i * 256;           // 0..1023
            int rr = t >> 3, cc = t & 7;
            cp16(base + swz(rr, cc), gA + (size_t)rr * DMODEL + cc * 8);
        }
#pragma unroll
        for (int i = 0; i < 8; i++) {
            int t = tid + i * 256;           // 0..2047
            int rr = t >> 3, cc = t & 7;
            cp16(base + 16384 + swz(rr, cc), gB + (size_t)rr * DMODEL + cc * 8);
        }
    };

    issue(0); cp_commit();

    const int sub = lane >> 3;
    const int rbA = (sub & 1) * 8 + (lane & 7);
    const int csA = sub >> 1;
    const int rbB = (lane >> 4) * 8 + (lane & 7);
    const int csB = (lane >> 3) & 1;

    for (int kb = 0; kb < 16; kb++) {
        if (kb + 1 < 16) {
            issue(kb + 1); cp_commit();
            cp_wait<1>();
        } else {
            cp_wait<0>();
        }
        __syncthreads();

        const uint32_t base = sb + (kb & 1) * GSTAGE;
#pragma unroll
        for (int kk = 0; kk < 4; kk++) {
            uint32_t af[4][4], bf[16];
            const int chA = kk * 2 + csA;
            const int chB = kk * 2 + csB;
#pragma unroll
            for (int mt = 0; mt < 4; mt++)
                ldm_x4(af[mt], base + swz(wm + mt * 16 + rbA, chA));
#pragma unroll
            for (int p = 0; p < 4; p++)
                ldm_x4(&bf[p * 4], base + 16384 + swz(wn + p * 16 + rbB, chB));
#pragma unroll
            for (int mt = 0; mt < 4; mt++)
#pragma unroll
                for (int nt = 0; nt < 8; nt++)
                    mma16816(acc[mt][nt], af[mt], &bf[nt * 2]);
        }
        __syncthreads();
    }

    // ---- epilogue ----
    if (sel == 3) {
#pragma unroll
        for (int mt = 0; mt < 4; mt++)
#pragma unroll
            for (int nt = 0; nt < 8; nt++) {
                int row = bm + wm + mt * 16 + (lane >> 2);
                int col = bn + wn + nt * 8 + (lane & 3) * 2;
                float2 bv = *(const float2*)&bias[col];
                float2 y01 = make_float2(acc[mt][nt][0] + bv.x, acc[mt][nt][1] + bv.y);
                float2 y23 = make_float2(acc[mt][nt][2] + bv.x, acc[mt][nt][3] + bv.y);
                *(float2*)&outf[(size_t)row * DMODEL + col] = y01;
                *(float2*)&outf[(size_t)(row + 8) * DMODEL + col] = y23;
            }
    } else {
        __half* dst = (sel == 0) ? g_qf : (sel == 1) ? g_kf : g_vf;
        // fold 1/sqrt(Dh) AND log2(e) into q so attention can use exp2
        const float qs = (sel == 0) ? (0.125f * 1.44269504f) : 1.0f;
#pragma unroll
        for (int mt = 0; mt < 4; mt++)
#pragma unroll
            for (int nt = 0; nt < 8; nt++) {
                int row = bm + wm + mt * 16 + (lane >> 2);
                int col = bn + wn + nt * 8 + (lane & 3) * 2;
                float2 bv = *(const float2*)&bias[col];
                int hh = col >> 6, dd = col & 63;
#pragma unroll
                for (int hf = 0; hf < 2; hf++) {
                    int r = row + hf * 8;
                    float y0 = (acc[mt][nt][hf * 2 + 0] + bv.x) * qs;
                    float y1 = (acc[mt][nt][hf * 2 + 1] + bv.y) * qs;
                    int bb = r >> 11, s = r & (SEQ - 1);
                    size_t idx = (((size_t)(bb * NHEAD + hh)) * SEQ + s) * DHEAD + dd;
                    *(uint32_t*)&dst[idx] = pack2h(y0, y1);
                }
            }
    }
}

// ---------------- Flash attention (fp16 mma, f16x2 exp2 softmax) ----------------
// CTA: 64 q rows, 4 warps (16 rows each). Key tiles of 64, 3-stage KV pipeline.
// smem: Q 8K | 3 x (K 8K | V 8K) = 56K -> up to 4 CTAs/SM.
#define FSTAGE 16384
#define FSMEM  (8192 + 3 * FSTAGE)

__global__ __launch_bounds__(128) void flash_f16()
{
    extern __shared__ __align__(128) char sm[];
    const uint32_t sb = smem_u32(sm);

    const int tid = threadIdx.x;
    const int wid = tid >> 5, lane = tid & 31;
    const int qbase = blockIdx.x * 64;
    const int h = blockIdx.y;
    const int b = blockIdx.z;
    const int wq = wid * 16;

    const size_t head = (size_t)(b * NHEAD + h) * SEQ;
    const __half* qf_g = g_qf + (head + qbase) * DHEAD;
    const __half* kf_g = g_kf + head * DHEAD;
    const __half* vf_g = g_vf + head * DHEAD;

    // ---- issue Q ----
#pragma unroll
    for (int i = 0; i < 4; i++) {
        int t = tid + i * 128;           // 0..511
        int rr = t >> 3, cc = t & 7;
        cp16(sb + swz(rr, cc), qf_g + (size_t)rr * DHEAD + cc * 8);
    }
    cp_commit();

    auto issue_kv = [&](int kt) {
        uint32_t base = sb + 8192 + (kt % 3) * FSTAGE;
        size_t k0 = (size_t)kt * 64 * DHEAD;
#pragma unroll
        for (int i = 0; i < 4; i++) {
            int t = tid + i * 128;       // 0..511
            int rr = t >> 3, cc = t & 7;
            uint32_t so = swz(rr, cc);
            size_t go = k0 + (size_t)rr * DHEAD + cc * 8;
            cp16(base + so,        kf_g + go);
            cp16(base + 8192 + so, vf_g + go);
        }
    };

    issue_kv(0); cp_commit();
    issue_kv(1); cp_commit();

    cp_wait<2>();      // Q ready
    __syncthreads();

    const int sub = lane >> 3;
    const int rbA = (sub & 1) * 8 + (lane & 7);
    const int csA = sub >> 1;
    const int rbB = (lane >> 4) * 8 + (lane & 7);
    const int csB = (lane >> 3) & 1;

    uint32_t qf[4][4];
#pragma unroll
    for (int kk = 0; kk < 4; kk++)
        ldm_x4(qf[kk], sb + swz(wq + rbA, kk * 2 + csA));

    float o[8][4];
#pragma unroll
    for (int nt = 0; nt < 8; nt++)
#pragma unroll
        for (int j = 0; j < 4; j++) o[nt][j] = 0.0f;
    float m0 = -1e30f, m1 = -1e30f, l0 = 0.0f, l1 = 0.0f;

    const int NT = SEQ / 64;
    for (int kt = 0; kt < NT; kt++) {
        cp_wait<1>();
        __syncthreads();
        if (kt + 2 < NT) issue_kv(kt + 2);
        cp_commit();

        const uint32_t kvb = sb + 8192 + (kt % 3) * FSTAGE;

        // ---- S = Q K^T (m16 x n64 per warp); scores already in log2 domain ----
        float s[8][4];
#pragma unroll
        for (int nt = 0; nt < 8; nt++)
#pragma unroll
            for (int j = 0; j < 4; j++) s[nt][j] = 0.0f;

#pragma unroll
        for (int kk = 0; kk < 4; kk++) {
            uint32_t kf[16];
            const int ch = kk * 2 + csB;
#pragma unroll
            for (int p = 0; p < 4; p++)
                ldm_x4(&kf[p * 4], kvb + swz(p * 16 + rbB, ch));
#pragma unroll
            for (int nt = 0; nt < 8; nt++)
                mma16816(s[nt], qf[kk], &kf[nt * 2]);
        }

        // ---- f16x2 online softmax (rows lane>>2 and lane>>2 + 8) ----
        // pack score pairs: row A = (s[nt][0], s[nt][1]), row B = (s[nt][2], s[nt][3])
        __half2 a2[8], b2[8];
#pragma unroll
        for (int nt = 0; nt < 8; nt++) {
            uint32_t ua = pack2h(s[nt][0], s[nt][1]);
            uint32_t ub = pack2h(s[nt][2], s[nt][3]);
            a2[nt] = *(__half2*)&ua;
            b2[nt] = *(__half2*)&ub;
        }
        // row max (vector tree + scalar finish + cross-lane)
        __half2 ma = __hmax2(__hmax2(__hmax2(a2[0], a2[1]), __hmax2(a2[2], a2[3])),
                             __hmax2(__hmax2(a2[4], a2[5]), __hmax2(a2[6], a2[7])));
        __half2 mb = __hmax2(__hmax2(__hmax2(b2[0], b2[1]), __hmax2(b2[2], b2[3])),
                             __hmax2(__hmax2(b2[4], b2[5]), __hmax2(b2[6], b2[7])));
        float mx0 = fmaxf(__low2float(ma), __high2float(ma));
        float mx1 = fmaxf(__low2float(mb), __high2float(mb));
        mx0 = fmaxf(mx0, __shfl_xor_sync(0xffffffffu, mx0, 1));
        mx0 = fmaxf(mx0, __shfl_xor_sync(0xffffffffu, mx0, 2));
        mx1 = fmaxf(mx1, __shfl_xor_sync(0xffffffffu, mx1, 1));
        mx1 = fmaxf(mx1, __shfl_xor_sync(0xffffffffu, mx1, 2));
        float M0 = fmaxf(m0, mx0), M1 = fmaxf(m1, mx1);
        float c0 = exp2f(m0 - M0), c1 = exp2f(m1 - M1);
        __half2 M0h = __float2half2_rn(M0), M1h = __float2half2_rn(M1);

        // exp2(s - M) in f16x2 -> these ARE the P fragments
#pragma unroll
        for (int nt = 0; nt < 8; nt++) {
            a2[nt] = h2exp2(__hsub2(a2[nt], M0h));
            b2[nt] = h2exp2(__hsub2(b2[nt], M1h));
        }
        // row sums (HADD2 tree, finish in fp32)
        __half2 sa = __hadd2(__hadd2(__hadd2(a2[0], a2[1]), __hadd2(a2[2], a2[3])),
                             __hadd2(__hadd2(a2[4], a2[5]), __hadd2(a2[6], a2[7])));
        __half2 sbv = __hadd2(__hadd2(__hadd2(b2[0], b2[1]), __hadd2(b2[2], b2[3])),
                              __hadd2(__hadd2(b2[4], b2[5]), __hadd2(b2[6], b2[7])));
        float sum0 = __low2float(sa) + __high2float(sa);
        float sum1 = __low2float(sbv) + __high2float(sbv);
        sum0 += __shfl_xor_sync(0xffffffffu, sum0, 1);
        sum0 += __shfl_xor_sync(0xffffffffu, sum0, 2);
        sum1 += __shfl_xor_sync(0xffffffffu, sum1, 1);
        sum1 += __shfl_xor_sync(0xffffffffu, sum1, 2);
        l0 = l0 * c0 + sum0; m0 = M0;
        l1 = l1 * c1 + sum1; m1 = M1;
#pragma unroll
        for (int nt = 0; nt < 8; nt++) {
            o[nt][0] *= c0; o[nt][1] *= c0;
            o[nt][2] *= c1; o[nt][3] *= c1;
        }

        // ---- P fragments: direct relabel of exp'd half2 ----
        uint32_t pf[4][4];
#pragma unroll
        for (int j = 0; j < 4; j++) {
            pf[j][0] = *(uint32_t*)&a2[2 * j];
            pf[j][1] = *(uint32_t*)&b2[2 * j];
            pf[j][2] = *(uint32_t*)&a2[2 * j + 1];
            pf[j][3] = *(uint32_t*)&b2[2 * j + 1];
        }

        // ---- O += P V ----
#pragma unroll
        for (int j = 0; j < 4; j++) {
            uint32_t vf[16];
#pragma unroll
            for (int i = 0; i < 4; i++)
                ldm_x4_t(&vf[i * 4], kvb + 8192 + swz(j * 16 + rbA, 2 * i + csA));
#pragma unroll
            for (int nt = 0; nt < 8; nt++)
                mma16816(o[nt], pf[j], &vf[nt * 2]);
        }
    }

    // ---- write attention output to [B,S,D] (single fp16) ----
    const float inv0 = 1.0f / l0, inv1 = 1.0f / l1;
#pragma unroll
    for (int nt = 0; nt < 8; nt++) {
        int col = h * 64 + nt * 8 + (lane & 3) * 2;
        int row0 = qbase + wq + (lane >> 2);
#pragma unroll
        for (int hf = 0; hf < 2; hf++) {
            int r = row0 + hf * 8;
            float inv = hf ? inv1 : inv0;
            float y0 = o[nt][hf * 2 + 0] * inv;
            float y1 = o[nt][hf * 2 + 1] * inv;
            size_t idx = ((size_t)b * SEQ + r) * DMODEL + col;
            *(uint32_t*)&g_af[idx] = pack2h(y0, y1);
        }
    }
}

// ---------------- launch ----------------
extern "C" void kernel_launch(void* const* d_in, const int* in_sizes, int n_in,
                              void* d_out, int out_size)
{
    const float* Q  = (const float*)d_in[0];
    const float* K  = (const float*)d_in[1];
    const float* V  = (const float*)d_in[2];
    const float* Wq = (const float*)d_in[3];
    const float* bq = (const float*)d_in[4];
    const float* Wk = (const float*)d_in[5];
    const float* bk = (const float*)d_in[6];
    const float* Wv = (const float*)d_in[7];
    const float* bv = (const float*)d_in[8];
    const float* Wo = (const float*)d_in[9];
    const float* bo = (const float*)d_in[10];
    float* out = (float*)d_out;

    static int attr_done = 0;
    if (!attr_done) {
        cudaFuncSetAttribute(gemm_f16, cudaFuncAttributeMaxDynamicSharedMemorySize, GSMEM);
        cudaFuncSetAttribute(flash_f16, cudaFuncAttributeMaxDynamicSharedMemorySize, FSMEM);
        attr_done = 1;
    }

    convert_inputs<<<dim3(XN / 8 / 256, 3), 256>>>(Q, K, V);
    convert_weights<<<dim3(WN / 8 / 256, 4), 256>>>(Wq, Wk, Wv, Wo);

    // Q, K, V projections in one launch (grid.z = sel)
    gemm_f16<<<dim3(DMODEL / 256, MTOT / 128, 3), 256, GSMEM>>>(bq, bk, bv, nullptr, 0);

    flash_f16<<<dim3(SEQ / 64, NHEAD, BATCH), 128, FSMEM>>>();

    // output projection
    gemm_f16<<<dim3(DMODEL / 256, MTOT / 128, 1), 256, GSMEM>>>(bo, bo, bo, out, 3);
}